// round 11
// baseline (speedup 1.0000x reference)
#include <cuda_runtime.h>
#include <cuda_bf16.h>
#include <cstdint>

typedef unsigned long long ull;

#define HW   3136
#define WID  56
#define NHD  8
#define CHN  8
#define SCALE 0.17677669529663687f  // (256/8)^-0.5

// Scratch (alloc-free rule: __device__ globals)
__device__ float g_qkv[16 * 192 * HW];   // (B, 192, H*W)
__device__ float g_hid[16 * 64  * HW];   // (B, 64, H*W)

// ---------------------------------------------------------------------------
// helpers
// ---------------------------------------------------------------------------
__device__ __forceinline__ ull pack2(float x) {
    ull r; unsigned u = __float_as_uint(x);
    asm("mov.b64 %0, {%1, %1};" : "=l"(r) : "r"(u));
    return r;
}
__device__ __forceinline__ ull pack2f(float a, float b) {
    ull r;
    asm("mov.b64 %0, {%1, %2};" : "=l"(r) : "f"(a), "f"(b));
    return r;
}
__device__ __forceinline__ void unpack2(ull v, float &a, float &b) {
    asm("mov.b64 {%0, %1}, %2;" : "=f"(a), "=f"(b) : "l"(v));
}
__device__ __forceinline__ void fma2(ull &d, ull a, ull b) {
    asm("fma.rn.f32x2 %0, %1, %2, %3;" : "=l"(d) : "l"(a), "l"(b), "l"(d));
}
__device__ __forceinline__ uint32_t smem_u32(const void* p) {
    uint32_t a;
    asm("{ .reg .u64 t; cvta.to.shared.u64 t, %1; cvt.u32.u64 %0, t; }"
        : "=r"(a) : "l"(p));
    return a;
}
// bf16 split: (x,y) -> packed hi bf16x2 (x low half) and lo bf16x2
__device__ __forceinline__ void split2(float x, float y, unsigned &hi2, unsigned &lo2) {
    __nv_bfloat16 xh = __float2bfloat16_rn(x);
    __nv_bfloat16 yh = __float2bfloat16_rn(y);
    float xr = x - __bfloat162float(xh);
    float yr = y - __bfloat162float(yh);
    __nv_bfloat162 h2 = __halves2bfloat162(xh, yh);
    __nv_bfloat162 l2 = __halves2bfloat162(__float2bfloat16_rn(xr), __float2bfloat16_rn(yr));
    hi2 = *reinterpret_cast<unsigned*>(&h2);
    lo2 = *reinterpret_cast<unsigned*>(&l2);
}
__device__ __forceinline__ void ldsm4(uint32_t (&r)[4], uint32_t addr) {
    asm volatile("ldmatrix.sync.aligned.m8n8.x4.shared.b16 {%0,%1,%2,%3}, [%4];"
        : "=r"(r[0]), "=r"(r[1]), "=r"(r[2]), "=r"(r[3]) : "r"(addr));
}
__device__ __forceinline__ void mma16816(float (&d)[4], const uint32_t (&a)[4],
                                         uint32_t b0, uint32_t b1) {
    asm volatile(
        "mma.sync.aligned.m16n8k16.row.col.f32.bf16.bf16.f32 "
        "{%0,%1,%2,%3}, {%4,%5,%6,%7}, {%8,%9}, {%0,%1,%2,%3};"
        : "+f"(d[0]), "+f"(d[1]), "+f"(d[2]), "+f"(d[3])
        : "r"(a[0]), "r"(a[1]), "r"(a[2]), "r"(a[3]), "r"(b0), "r"(b1));
}
__device__ __forceinline__ void sts128(uint32_t addr, unsigned a, unsigned b,
                                       unsigned c, unsigned d) {
    asm volatile("st.shared.v4.b32 [%0], {%1,%2,%3,%4};"
                 :: "r"(addr), "r"(a), "r"(b), "r"(c), "r"(d));
}

// ---------------------------------------------------------------------------
// HMMA bf16x3 GEMM:  C[b, ch, pix] = sum_k W[ch,k] * X[b,k,pix] + bias[ch]
// Block: 128 pixels x NTILE channels (FULL N, one block per m-tile).
// 512 threads = 16 warps (4 m-warps x 4 n-warps), warp tile 32 x NTILE/4.
// A tile (X^T, bf16 hi/lo) loaded/split/stored ONCE per block (no n-tile
// duplication). 80B row stride: conflict-free STS.128 + ldmatrix.
// ---------------------------------------------------------------------------
template<int NTILE, int KTOT>
__global__ void __launch_bounds__(512, 1)
gemm_hmma(const float* __restrict__ X, const float* __restrict__ W,
          const float* __restrict__ bias, float* __restrict__ C)
{
    constexpr int KT    = KTOT / 32;        // k-tiles
    constexpr int WN    = NTILE / 4;        // warp n extent
    constexpr int NFRAG = WN / 8;           // n8 fragments per warp
    constexpr int NPAIR = NFRAG / 2;
    constexpr int ABUF  = 2 * 128 * 80;     // hi+lo, one buffer
    constexpr int BROW  = NTILE * 80;
    constexpr int BBUF  = 2 * BROW;
    constexpr int BOFF  = 2 * ABUF;         // B region start

    extern __shared__ char dyn[];
    const uint32_t sb = smem_u32(dyn);

    const int tid  = threadIdx.x;
    const int wid  = tid >> 5;
    const int lane = tid & 31;
    const int wm   = wid & 3;               // m-warp 0..3
    const int wn   = wid >> 2;              // n-warp 0..3
    const int m0   = blockIdx.x * 128;
    const int b    = blockIdx.z;

    const float* Xb = X + (long)b * KTOT * HW;
    float*       Cb = C + (long)b * NTILE * HW;

    // loader roles: X — 512 threads, 128 pixels x 4 k-quarters (8 k each)
    const int px    = tid & 127;
    const int khx   = tid >> 7;             // 0..3
    const int pixg  = min(m0 + px, HW - 1);
    // W — NTILE*2 threads, 16 k each (2 halves)
    const bool wAct = tid < NTILE * 2;
    const int wch   = tid >> 1;
    const int khw   = tid & 1;

    float acc[2][NFRAG][4];
    #pragma unroll
    for (int i = 0; i < 2; i++)
        #pragma unroll
        for (int j = 0; j < NFRAG; j++)
            #pragma unroll
            for (int e = 0; e < 4; e++) acc[i][j][e] = 0.f;

    float xv[8];
    float4 wv[4];

    auto loadRegs = [&](int t) {
        const int kx = t * 32 + khx * 8;
        #pragma unroll
        for (int j = 0; j < 8; j++)
            xv[j] = Xb[(long)(kx + j) * HW + pixg];
        if (wAct) {
            const long wbase = (long)wch * KTOT + t * 32 + khw * 16;
            #pragma unroll
            for (int j = 0; j < 4; j++)
                wv[j] = *(const float4*)(W + wbase + 4 * j);
        }
    };
    auto stsTile = [&](int buf) {
        // X: 8 k values -> 4 pairs -> 1 STS.128 (hi) + 1 (lo)
        const uint32_t Ahi = sb + buf * ABUF;
        const uint32_t Alo = Ahi + 128 * 80;
        {
            unsigned h[4], l[4];
            #pragma unroll
            for (int k2 = 0; k2 < 4; k2++)
                split2(xv[2 * k2], xv[2 * k2 + 1], h[k2], l[k2]);
            const uint32_t off = (uint32_t)(px * 80 + khx * 16);
            sts128(Ahi + off, h[0], h[1], h[2], h[3]);
            sts128(Alo + off, l[0], l[1], l[2], l[3]);
        }
        if (wAct) {
            const uint32_t Bhi = sb + BOFF + buf * BBUF;
            const uint32_t Blo = Bhi + BROW;
            const float wf[16] = { wv[0].x, wv[0].y, wv[0].z, wv[0].w,
                                   wv[1].x, wv[1].y, wv[1].z, wv[1].w,
                                   wv[2].x, wv[2].y, wv[2].z, wv[2].w,
                                   wv[3].x, wv[3].y, wv[3].z, wv[3].w };
            #pragma unroll
            for (int g = 0; g < 2; g++) {
                unsigned h[4], l[4];
                #pragma unroll
                for (int k2 = 0; k2 < 4; k2++)
                    split2(wf[g * 8 + 2 * k2], wf[g * 8 + 2 * k2 + 1], h[k2], l[k2]);
                const uint32_t off = (uint32_t)(wch * 80 + khw * 32 + g * 16);
                sts128(Bhi + off, h[0], h[1], h[2], h[3]);
                sts128(Blo + off, l[0], l[1], l[2], l[3]);
            }
        }
    };
    auto compute = [&](int buf) {
        const uint32_t Ahi = sb + buf * ABUF;
        const uint32_t Alo = Ahi + 128 * 80;
        const uint32_t Bhi = sb + BOFF + buf * BBUF;
        const uint32_t Blo = Bhi + BROW;
        const int lrow = lane & 15;
        const uint32_t kb0 = (uint32_t)((lane >> 4) << 4);   // +16B for hi-k lanes
        #pragma unroll
        for (int s = 0; s < 2; s++) {
            const uint32_t kb = kb0 + 32 * s;
            uint32_t ah[2][4], al[2][4];
            #pragma unroll
            for (int mf = 0; mf < 2; mf++) {
                const uint32_t ro = (uint32_t)((wm * 32 + mf * 16 + lrow) * 80) + kb;
                ldsm4(ah[mf], Ahi + ro);
                ldsm4(al[mf], Alo + ro);
            }
            #pragma unroll
            for (int j = 0; j < NPAIR; j++) {
                const uint32_t ro = (uint32_t)((wn * WN + j * 16 + lrow) * 80) + kb;
                uint32_t bh[4], bl[4];
                ldsm4(bh, Bhi + ro);
                ldsm4(bl, Blo + ro);
                #pragma unroll
                for (int mf = 0; mf < 2; mf++) {
                    mma16816(acc[mf][2*j],   ah[mf], bh[0], bh[2]);
                    mma16816(acc[mf][2*j+1], ah[mf], bh[1], bh[3]);
                    mma16816(acc[mf][2*j],   ah[mf], bl[0], bl[2]);
                    mma16816(acc[mf][2*j+1], ah[mf], bl[1], bl[3]);
                    mma16816(acc[mf][2*j],   al[mf], bh[0], bh[2]);
                    mma16816(acc[mf][2*j+1], al[mf], bh[1], bh[3]);
                }
            }
        }
    };

    // ---- pipeline ----
    loadRegs(0);
    stsTile(0);
    __syncthreads();
    for (int t = 0; t < KT; t++) {
        if (t + 1 < KT) loadRegs(t + 1);
        compute(t & 1);
        if (t + 1 < KT) {
            stsTile((t + 1) & 1);
            __syncthreads();
        }
    }

    // ---- epilogue ----
    const int r0 = lane >> 2;
    const int c0 = 2 * (lane & 3);
    #pragma unroll
    for (int nf = 0; nf < NFRAG; nf++) {
        const int ch = wn * WN + nf * 8 + c0;
        const float b0 = bias[ch], b1 = bias[ch + 1];
        float* p0 = Cb + (long)ch * HW;
        float* p1 = p0 + HW;
        #pragma unroll
        for (int mf = 0; mf < 2; mf++) {
            const int pr = m0 + wm * 32 + mf * 16 + r0;
            if (pr < HW) {
                p0[pr] = acc[mf][nf][0] + b0;
                p1[pr] = acc[mf][nf][1] + b1;
            }
            if (pr + 8 < HW) {
                p0[pr + 8] = acc[mf][nf][2] + b0;
                p1[pr + 8] = acc[mf][nf][3] + b1;
            }
        }
    }
}

// ---------------------------------------------------------------------------
// Fused sliding attention v2 (unchanged from R6)
// ---------------------------------------------------------------------------
#define AT_ROWS 8
#define AT_HROW (AT_ROWS + 2)

__global__ void __launch_bounds__(224)
attn2(const float* __restrict__ qkv,
      const float* __restrict__ dc_b,
      const float* __restrict__ dc1_w,
      const float* __restrict__ dc1_b,
      const float* __restrict__ rpb,
      float* __restrict__ hid)
{
    __shared__ float sk[CHN][AT_HROW][58];
    __shared__ float sv[CHN][AT_HROW][58];
    __shared__ ull   wp[72][10];
    __shared__ ull   bk2[72];
    __shared__ ull   bv2[72];

    const int tid = threadIdx.x;
    const int h = blockIdx.y;
    const int b = blockIdx.z;
    const int y0 = blockIdx.x * AT_ROWS;

    if (tid < 72) {
        const int a = tid - (tid / 9) * 9;
        const float cb = dc_b[tid] + dc1_b[tid];
        bv2[tid] = pack2(cb);
        bk2[tid] = pack2(cb + rpb[h * 9 + a]);
        #pragma unroll
        for (int t = 0; t < 9; t++) {
            float w = dc1_w[tid * 9 + t] + ((t == a) ? 1.f : 0.f);
            wp[tid][t] = pack2(w);
        }
        wp[tid][9] = 0ULL;
    }

    {
        const float* base = qkv + ((long)(b * 192 + h * 24 + 8)) * HW;
        for (int i = tid; i < AT_HROW * 58; i += 224) {
            const int r = i / 58, s = i - r * 58;
            const int gy = y0 - 1 + r, gx = s - 1;
            const bool ok = (gy >= 0) & (gy < WID) & (gx >= 0) & (gx < WID);
            const int off = ok ? gy * WID + gx : 0;
            #pragma unroll
            for (int c = 0; c < CHN; c++) {
                sk[c][r][s] = ok ? base[c * HW + off]       : 0.f;
                sv[c][r][s] = ok ? base[(8 + c) * HW + off] : 0.f;
            }
        }
    }

    const int tx  = tid % 28;
    const int tyy = tid / 28;
    const int px0 = tx * 2;
    const int gy  = y0 + tyy;
    const int pix = gy * WID + px0;

    ull q2[CHN];
    {
        const float* qp = qkv + ((long)(b * 192 + h * 24)) * HW + pix;
        #pragma unroll
        for (int c = 0; c < CHN; c++) {
            const float2 qv = *(const float2*)(qp + (long)c * HW);
            q2[c] = pack2f(qv.x * SCALE, qv.y * SCALE);
        }
    }
    __syncthreads();

    ull logit2[9];
    #pragma unroll
    for (int a = 0; a < 9; a++) logit2[a] = 0ULL;

    #pragma unroll 1
    for (int c = 0; c < CHN; c++) {
        ull nb[9];
        #pragma unroll
        for (int dy = 0; dy < 3; dy++) {
            const float* rp = &sk[c][tyy + dy][px0];
            const ull A  = *(const ull*)rp;
            const ull Cc = *(const ull*)(rp + 2);
            nb[dy * 3 + 0] = A;
            nb[dy * 3 + 1] = (A >> 32) | (Cc << 32);
            nb[dy * 3 + 2] = Cc;
        }
        #pragma unroll
        for (int a = 0; a < 9; a++) {
            const int ca = c * 9 + a;
            const ulonglong2 w01 = *(const ulonglong2*)&wp[ca][0];
            const ulonglong2 w23 = *(const ulonglong2*)&wp[ca][2];
            const ulonglong2 w45 = *(const ulonglong2*)&wp[ca][4];
            const ulonglong2 w67 = *(const ulonglong2*)&wp[ca][6];
            const ulonglong2 w8p = *(const ulonglong2*)&wp[ca][8];
            ull kv = bk2[ca];
            fma2(kv, w01.x, nb[0]); fma2(kv, w01.y, nb[1]);
            fma2(kv, w23.x, nb[2]); fma2(kv, w23.y, nb[3]);
            fma2(kv, w45.x, nb[4]); fma2(kv, w45.y, nb[5]);
            fma2(kv, w67.x, nb[6]); fma2(kv, w67.y, nb[7]);
            fma2(kv, w8p.x, nb[8]);
            fma2(logit2[a], q2[c], kv);
        }
    }

    ull p2[9];
    {
        float l0[9], l1[9];
        #pragma unroll
        for (int a = 0; a < 9; a++) unpack2(logit2[a], l0[a], l1[a]);
        float m0 = l0[0], m1 = l1[0];
        #pragma unroll
        for (int a = 1; a < 9; a++) { m0 = fmaxf(m0, l0[a]); m1 = fmaxf(m1, l1[a]); }
        float s0 = 0.f, s1 = 0.f;
        #pragma unroll
        for (int a = 0; a < 9; a++) {
            l0[a] = __expf(l0[a] - m0); s0 += l0[a];
            l1[a] = __expf(l1[a] - m1); s1 += l1[a];
        }
        const float i0 = 1.f / s0, i1 = 1.f / s1;
        #pragma unroll
        for (int a = 0; a < 9; a++) p2[a] = pack2f(l0[a] * i0, l1[a] * i1);
    }

    float* hb = hid + ((long)(b * 64 + h * 8)) * HW + pix;
    #pragma unroll 1
    for (int c = 0; c < CHN; c++) {
        ull nb[9];
        #pragma unroll
        for (int dy = 0; dy < 3; dy++) {
            const float* rp = &sv[c][tyy + dy][px0];
            const ull A  = *(const ull*)rp;
            const ull Cc = *(const ull*)(rp + 2);
            nb[dy * 3 + 0] = A;
            nb[dy * 3 + 1] = (A >> 32) | (Cc << 32);
            nb[dy * 3 + 2] = Cc;
        }
        ull o2 = 0ULL;
        #pragma unroll
        for (int a = 0; a < 9; a++) {
            const int ca = c * 9 + a;
            const ulonglong2 w01 = *(const ulonglong2*)&wp[ca][0];
            const ulonglong2 w23 = *(const ulonglong2*)&wp[ca][2];
            const ulonglong2 w45 = *(const ulonglong2*)&wp[ca][4];
            const ulonglong2 w67 = *(const ulonglong2*)&wp[ca][6];
            const ulonglong2 w8p = *(const ulonglong2*)&wp[ca][8];
            ull vv = bv2[ca];
            fma2(vv, w01.x, nb[0]); fma2(vv, w01.y, nb[1]);
            fma2(vv, w23.x, nb[2]); fma2(vv, w23.y, nb[3]);
            fma2(vv, w45.x, nb[4]); fma2(vv, w45.y, nb[5]);
            fma2(vv, w67.x, nb[6]); fma2(vv, w67.y, nb[7]);
            fma2(vv, w8p.x, nb[8]);
            fma2(o2, p2[a], vv);
        }
        float o0, o1; unpack2(o2, o0, o1);
        *(float2*)(hb + (long)c * HW) = make_float2(o0, o1);
    }
}

extern "C" void kernel_launch(void* const* d_in, const int* in_sizes, int n_in,
                              void* d_out, int out_size)
{
    const float* x      = (const float*)d_in[0];  // (16,256,56,56)
    const float* qkv_w  = (const float*)d_in[1];  // (192,256)
    const float* qkv_b  = (const float*)d_in[2];  // (192)
    const float* dc_b   = (const float*)d_in[3];  // (72)
    const float* dc1_w  = (const float*)d_in[4];  // (72,1,3,3)
    const float* dc1_b  = (const float*)d_in[5];  // (72)
    const float* rpb    = (const float*)d_in[6];  // (1,8,1,9,1,1)
    const float* proj_w = (const float*)d_in[7];  // (256,64)
    const float* proj_b = (const float*)d_in[8];  // (256)
    float* out = (float*)d_out;                   // (16,256,56,56)

    float *qkv_p, *hid_p;
    cudaGetSymbolAddress((void**)&qkv_p, g_qkv);
    cudaGetSymbolAddress((void**)&hid_p, g_hid);

    // smem: 2 A buffers (2*20480) + 2 B buffers
    const int SMEM_QKV  = 2 * (2 * 128 * 80) + 2 * (2 * 192 * 80);  // 102,400
    const int SMEM_PROJ = 2 * (2 * 128 * 80) + 2 * (2 * 256 * 80);  // 122,880
    cudaFuncSetAttribute(gemm_hmma<192, 256>,
                         cudaFuncAttributeMaxDynamicSharedMemorySize, SMEM_QKV);
    cudaFuncSetAttribute(gemm_hmma<256, 64>,
                         cudaFuncAttributeMaxDynamicSharedMemorySize, SMEM_PROJ);

    // 1) QKV: C(192,3136) = qkv_w(192,256) @ x(256,3136), per batch
    gemm_hmma<192, 256><<<dim3(25, 1, 16), 512, SMEM_QKV>>>(x, qkv_w, qkv_b, qkv_p);

    // 2) Fused sliding attention
    attn2<<<dim3(WID / AT_ROWS, NHD, 16), 224>>>(
        qkv_p, dc_b, dc1_w, dc1_b, rpb, hid_p);

    // 3) Proj: out(256,3136) = proj_w(256,64) @ hid(64,3136), per batch
    gemm_hmma<256, 64><<<dim3(25, 1, 16), 512, SMEM_PROJ>>>(hid_p, proj_w, proj_b, out);
}

// round 12
// speedup vs baseline: 1.0751x; 1.0751x over previous
#include <cuda_runtime.h>
#include <cuda_bf16.h>
#include <cstdint>

typedef unsigned long long ull;

#define HW   3136
#define WID  56
#define NHD  8
#define CHN  8
#define SCALE 0.17677669529663687f  // (256/8)^-0.5

// Scratch (alloc-free rule: __device__ globals)
__device__ float g_qkv[16 * 192 * HW];   // (B, 192, H*W)
__device__ float g_hid[16 * 64  * HW];   // (B, 64, H*W)
// Pre-packed bf16 hi/lo weight images (smem layout chunks):
// [tile][hi rows 0..N-1 (16 words each)][lo rows 0..N-1]
__device__ uint4 g_wq[(256 / 32) * 192 * 8];   // qkv_w packed: 12288 uint4
__device__ uint4 g_wp[(64  / 32) * 256 * 8];   // proj_w packed: 4096 uint4

// ---------------------------------------------------------------------------
// helpers
// ---------------------------------------------------------------------------
__device__ __forceinline__ ull pack2(float x) {
    ull r; unsigned u = __float_as_uint(x);
    asm("mov.b64 %0, {%1, %1};" : "=l"(r) : "r"(u));
    return r;
}
__device__ __forceinline__ ull pack2f(float a, float b) {
    ull r;
    asm("mov.b64 %0, {%1, %2};" : "=l"(r) : "f"(a), "f"(b));
    return r;
}
__device__ __forceinline__ void unpack2(ull v, float &a, float &b) {
    asm("mov.b64 {%0, %1}, %2;" : "=f"(a), "=f"(b) : "l"(v));
}
__device__ __forceinline__ void fma2(ull &d, ull a, ull b) {
    asm("fma.rn.f32x2 %0, %1, %2, %3;" : "=l"(d) : "l"(a), "l"(b), "l"(d));
}
__device__ __forceinline__ uint32_t smem_u32(const void* p) {
    uint32_t a;
    asm("{ .reg .u64 t; cvta.to.shared.u64 t, %1; cvt.u32.u64 %0, t; }"
        : "=r"(a) : "l"(p));
    return a;
}
// bf16 split: (x,y) -> packed hi bf16x2 (x low half) and lo bf16x2
__device__ __forceinline__ void split2(float x, float y, unsigned &hi2, unsigned &lo2) {
    __nv_bfloat16 xh = __float2bfloat16_rn(x);
    __nv_bfloat16 yh = __float2bfloat16_rn(y);
    float xr = x - __bfloat162float(xh);
    float yr = y - __bfloat162float(yh);
    __nv_bfloat162 h2 = __halves2bfloat162(xh, yh);
    __nv_bfloat162 l2 = __halves2bfloat162(__float2bfloat16_rn(xr), __float2bfloat16_rn(yr));
    hi2 = *reinterpret_cast<unsigned*>(&h2);
    lo2 = *reinterpret_cast<unsigned*>(&l2);
}
__device__ __forceinline__ void ldsm4(uint32_t (&r)[4], uint32_t addr) {
    asm volatile("ldmatrix.sync.aligned.m8n8.x4.shared.b16 {%0,%1,%2,%3}, [%4];"
        : "=r"(r[0]), "=r"(r[1]), "=r"(r[2]), "=r"(r[3]) : "r"(addr));
}
__device__ __forceinline__ void mma16816(float (&d)[4], const uint32_t (&a)[4],
                                         uint32_t b0, uint32_t b1) {
    asm volatile(
        "mma.sync.aligned.m16n8k16.row.col.f32.bf16.bf16.f32 "
        "{%0,%1,%2,%3}, {%4,%5,%6,%7}, {%8,%9}, {%0,%1,%2,%3};"
        : "+f"(d[0]), "+f"(d[1]), "+f"(d[2]), "+f"(d[3])
        : "r"(a[0]), "r"(a[1]), "r"(a[2]), "r"(a[3]), "r"(b0), "r"(b1));
}
__device__ __forceinline__ void sts128(uint32_t addr, unsigned a, unsigned b,
                                       unsigned c, unsigned d) {
    asm volatile("st.shared.v4.b32 [%0], {%1,%2,%3,%4};"
                 :: "r"(addr), "r"(a), "r"(b), "r"(c), "r"(d));
}

// ---------------------------------------------------------------------------
// W pre-pack: fp32 (NCH x KTOT) -> per-32k-tile bf16 hi/lo smem-image chunks.
// word layout: tile*(NCH*32) + plane*(NCH*16) + row*16 + pair
// ---------------------------------------------------------------------------
__global__ void pack_w(const float* __restrict__ W, uint4* __restrict__ dst,
                       int NCH, int KTOT)
{
    const int idx = blockIdx.x * 256 + threadIdx.x;
    const int npairs = NCH * (KTOT >> 1);
    if (idx >= npairs) return;
    const int ch = idx / (KTOT >> 1);
    const int pr = idx - ch * (KTOT >> 1);
    const int t  = pr >> 4;
    const int p  = pr & 15;
    unsigned h, l;
    split2(W[ch * KTOT + 2 * pr], W[ch * KTOT + 2 * pr + 1], h, l);
    uint32_t* d32 = (uint32_t*)dst;
    const uint32_t base = (uint32_t)(t * NCH * 32 + ch * 16 + p);
    d32[base] = h;
    d32[base + NCH * 16] = l;
}

// ---------------------------------------------------------------------------
// HMMA bf16x3 GEMM:  C[b, ch, pix] = sum_k W[ch,k] * X[b,k,pix] + bias[ch]
// Block: 64 pixels x NTILE channels; 256 threads = 8 warps (2m x 4n).
// HW = 49*64 exactly -> no guards. A (X^T bf16 hi/lo) split in-register;
// B copied from pre-packed gmem image. 80B row stride (conflict-free ldsm).
// ---------------------------------------------------------------------------
template<int NTILE, int NCHTOT, int KTOT>
__global__ void __launch_bounds__(256, 2)
gemm_hmma(const float* __restrict__ X, const uint4* __restrict__ Wp,
          const float* __restrict__ bias, float* __restrict__ C)
{
    constexpr int KT     = KTOT / 32;
    constexpr int WN     = NTILE / 4;
    constexpr int NFRAG  = WN / 8;
    constexpr int NPAIR  = NFRAG / 2;
    constexpr int ABUF   = 2 * 64 * 80;          // hi+lo A planes
    constexpr int BROW   = NTILE * 80;
    constexpr int BBUF   = 2 * BROW;
    constexpr int BOFF   = 2 * ABUF;
    constexpr int WCHUNK = NTILE / 32;           // uint4 chunks per thread per tile

    extern __shared__ char dyn[];
    const uint32_t sb = smem_u32(dyn);

    const int tid  = threadIdx.x;
    const int wid  = tid >> 5;
    const int lane = tid & 31;
    const int wm   = wid & 1;                    // m-warp 0..1
    const int wn   = wid >> 1;                   // n-warp 0..3
    const int m0   = blockIdx.x * 64;
    const int n0   = blockIdx.y * NTILE;
    const int b    = blockIdx.z;

    const float* Xb = X + (long)b * KTOT * HW;
    float*       Cb = C + (long)b * NCHTOT * HW;

    // A loader: px = tid&63, k-quarter = tid>>6 (8 consecutive k)
    const int px  = tid & 63;
    const int khx = tid >> 6;
    const float* xPtr = Xb + (long)(khx * 8) * HW + m0 + px;

    float acc[2][NFRAG][4];
    #pragma unroll
    for (int i = 0; i < 2; i++)
        #pragma unroll
        for (int j = 0; j < NFRAG; j++)
            #pragma unroll
            for (int e = 0; e < 4; e++) acc[i][j][e] = 0.f;

    float xv[8];
    uint4 wq[WCHUNK];

    auto loadRegs = [&](int t) {
        const float* xp = xPtr + (long)(t * 32) * HW;
        #pragma unroll
        for (int j = 0; j < 8; j++)
            xv[j] = xp[(long)j * HW];
        // B: pre-packed chunks. chunk c -> plane, row (within NTILE), seg
        #pragma unroll
        for (int i = 0; i < WCHUNK; i++) {
            const int c     = tid + (i << 8);
            const int plane = c >= NTILE * 4;
            const int rc    = c - plane * NTILE * 4;
            const int row   = rc >> 2;
            const int seg   = rc & 3;
            wq[i] = Wp[t * (NCHTOT * 8) + plane * (NCHTOT * 4) + (n0 + row) * 4 + seg];
        }
    };
    auto stsTile = [&](int buf) {
        const uint32_t Ahi = sb + buf * ABUF;
        const uint32_t Alo = Ahi + 64 * 80;
        {
            unsigned h[4], l[4];
            #pragma unroll
            for (int k2 = 0; k2 < 4; k2++)
                split2(xv[2 * k2], xv[2 * k2 + 1], h[k2], l[k2]);
            const uint32_t off = (uint32_t)(px * 80 + khx * 16);
            sts128(Ahi + off, h[0], h[1], h[2], h[3]);
            sts128(Alo + off, l[0], l[1], l[2], l[3]);
        }
        const uint32_t Bhi = sb + BOFF + buf * BBUF;
        const uint32_t Blo = Bhi + BROW;
        #pragma unroll
        for (int i = 0; i < WCHUNK; i++) {
            const int c     = tid + (i << 8);
            const int plane = c >= NTILE * 4;
            const int rc    = c - plane * NTILE * 4;
            const int row   = rc >> 2;
            const int seg   = rc & 3;
            const uint32_t addr = (plane ? Blo : Bhi) + (uint32_t)(row * 80 + seg * 16);
            sts128(addr, wq[i].x, wq[i].y, wq[i].z, wq[i].w);
        }
    };
    auto compute = [&](int buf) {
        const uint32_t Ahi = sb + buf * ABUF;
        const uint32_t Alo = Ahi + 64 * 80;
        const uint32_t Bhi = sb + BOFF + buf * BBUF;
        const uint32_t Blo = Bhi + BROW;
        const int lrow = lane & 15;
        const uint32_t kb0 = (uint32_t)((lane >> 4) << 4);
        #pragma unroll
        for (int s = 0; s < 2; s++) {
            const uint32_t kb = kb0 + 32 * s;
            uint32_t ah[2][4], al[2][4];
            #pragma unroll
            for (int mf = 0; mf < 2; mf++) {
                const uint32_t ro = (uint32_t)((wm * 32 + mf * 16 + lrow) * 80) + kb;
                ldsm4(ah[mf], Ahi + ro);
                ldsm4(al[mf], Alo + ro);
            }
            #pragma unroll
            for (int j = 0; j < NPAIR; j++) {
                const uint32_t ro = (uint32_t)((wn * WN + j * 16 + lrow) * 80) + kb;
                uint32_t bh[4], bl[4];
                ldsm4(bh, Bhi + ro);
                ldsm4(bl, Blo + ro);
                #pragma unroll
                for (int mf = 0; mf < 2; mf++) {
                    mma16816(acc[mf][2*j],   ah[mf], bh[0], bh[2]);
                    mma16816(acc[mf][2*j+1], ah[mf], bh[1], bh[3]);
                    mma16816(acc[mf][2*j],   ah[mf], bl[0], bl[2]);
                    mma16816(acc[mf][2*j+1], ah[mf], bl[1], bl[3]);
                    mma16816(acc[mf][2*j],   al[mf], bh[0], bh[2]);
                    mma16816(acc[mf][2*j+1], al[mf], bh[1], bh[3]);
                }
            }
        }
    };

    // ---- pipeline ----
    loadRegs(0);
    stsTile(0);
    __syncthreads();
    for (int t = 0; t < KT; t++) {
        if (t + 1 < KT) loadRegs(t + 1);
        compute(t & 1);
        if (t + 1 < KT) {
            stsTile((t + 1) & 1);
            __syncthreads();
        }
    }

    // ---- epilogue (no guards: HW = 49*64) ----
    const int r0 = lane >> 2;
    const int c0 = 2 * (lane & 3);
    #pragma unroll
    for (int nf = 0; nf < NFRAG; nf++) {
        const int ch = n0 + wn * WN + nf * 8 + c0;
        const float b0 = bias[ch], b1 = bias[ch + 1];
        float* p0 = Cb + (long)ch * HW;
        float* p1 = p0 + HW;
        #pragma unroll
        for (int mf = 0; mf < 2; mf++) {
            const int pr = m0 + wm * 32 + mf * 16 + r0;
            p0[pr]     = acc[mf][nf][0] + b0;
            p1[pr]     = acc[mf][nf][1] + b1;
            p0[pr + 8] = acc[mf][nf][2] + b0;
            p1[pr + 8] = acc[mf][nf][3] + b1;
        }
    }
}

// ---------------------------------------------------------------------------
// Fused sliding attention v2 (unchanged from R6)
// ---------------------------------------------------------------------------
#define AT_ROWS 8
#define AT_HROW (AT_ROWS + 2)

__global__ void __launch_bounds__(224)
attn2(const float* __restrict__ qkv,
      const float* __restrict__ dc_b,
      const float* __restrict__ dc1_w,
      const float* __restrict__ dc1_b,
      const float* __restrict__ rpb,
      float* __restrict__ hid)
{
    __shared__ float sk[CHN][AT_HROW][58];
    __shared__ float sv[CHN][AT_HROW][58];
    __shared__ ull   wp[72][10];
    __shared__ ull   bk2[72];
    __shared__ ull   bv2[72];

    const int tid = threadIdx.x;
    const int h = blockIdx.y;
    const int b = blockIdx.z;
    const int y0 = blockIdx.x * AT_ROWS;

    if (tid < 72) {
        const int a = tid - (tid / 9) * 9;
        const float cb = dc_b[tid] + dc1_b[tid];
        bv2[tid] = pack2(cb);
        bk2[tid] = pack2(cb + rpb[h * 9 + a]);
        #pragma unroll
        for (int t = 0; t < 9; t++) {
            float w = dc1_w[tid * 9 + t] + ((t == a) ? 1.f : 0.f);
            wp[tid][t] = pack2(w);
        }
        wp[tid][9] = 0ULL;
    }

    {
        const float* base = qkv + ((long)(b * 192 + h * 24 + 8)) * HW;
        for (int i = tid; i < AT_HROW * 58; i += 224) {
            const int r = i / 58, s = i - r * 58;
            const int gy = y0 - 1 + r, gx = s - 1;
            const bool ok = (gy >= 0) & (gy < WID) & (gx >= 0) & (gx < WID);
            const int off = ok ? gy * WID + gx : 0;
            #pragma unroll
            for (int c = 0; c < CHN; c++) {
                sk[c][r][s] = ok ? base[c * HW + off]       : 0.f;
                sv[c][r][s] = ok ? base[(8 + c) * HW + off] : 0.f;
            }
        }
    }

    const int tx  = tid % 28;
    const int tyy = tid / 28;
    const int px0 = tx * 2;
    const int gy  = y0 + tyy;
    const int pix = gy * WID + px0;

    ull q2[CHN];
    {
        const float* qp = qkv + ((long)(b * 192 + h * 24)) * HW + pix;
        #pragma unroll
        for (int c = 0; c < CHN; c++) {
            const float2 qv = *(const float2*)(qp + (long)c * HW);
            q2[c] = pack2f(qv.x * SCALE, qv.y * SCALE);
        }
    }
    __syncthreads();

    ull logit2[9];
    #pragma unroll
    for (int a = 0; a < 9; a++) logit2[a] = 0ULL;

    #pragma unroll 1
    for (int c = 0; c < CHN; c++) {
        ull nb[9];
        #pragma unroll
        for (int dy = 0; dy < 3; dy++) {
            const float* rp = &sk[c][tyy + dy][px0];
            const ull A  = *(const ull*)rp;
            const ull Cc = *(const ull*)(rp + 2);
            nb[dy * 3 + 0] = A;
            nb[dy * 3 + 1] = (A >> 32) | (Cc << 32);
            nb[dy * 3 + 2] = Cc;
        }
        #pragma unroll
        for (int a = 0; a < 9; a++) {
            const int ca = c * 9 + a;
            const ulonglong2 w01 = *(const ulonglong2*)&wp[ca][0];
            const ulonglong2 w23 = *(const ulonglong2*)&wp[ca][2];
            const ulonglong2 w45 = *(const ulonglong2*)&wp[ca][4];
            const ulonglong2 w67 = *(const ulonglong2*)&wp[ca][6];
            const ulonglong2 w8p = *(const ulonglong2*)&wp[ca][8];
            ull kv = bk2[ca];
            fma2(kv, w01.x, nb[0]); fma2(kv, w01.y, nb[1]);
            fma2(kv, w23.x, nb[2]); fma2(kv, w23.y, nb[3]);
            fma2(kv, w45.x, nb[4]); fma2(kv, w45.y, nb[5]);
            fma2(kv, w67.x, nb[6]); fma2(kv, w67.y, nb[7]);
            fma2(kv, w8p.x, nb[8]);
            fma2(logit2[a], q2[c], kv);
        }
    }

    ull p2[9];
    {
        float l0[9], l1[9];
        #pragma unroll
        for (int a = 0; a < 9; a++) unpack2(logit2[a], l0[a], l1[a]);
        float m0 = l0[0], m1 = l1[0];
        #pragma unroll
        for (int a = 1; a < 9; a++) { m0 = fmaxf(m0, l0[a]); m1 = fmaxf(m1, l1[a]); }
        float s0 = 0.f, s1 = 0.f;
        #pragma unroll
        for (int a = 0; a < 9; a++) {
            l0[a] = __expf(l0[a] - m0); s0 += l0[a];
            l1[a] = __expf(l1[a] - m1); s1 += l1[a];
        }
        const float i0 = 1.f / s0, i1 = 1.f / s1;
        #pragma unroll
        for (int a = 0; a < 9; a++) p2[a] = pack2f(l0[a] * i0, l1[a] * i1);
    }

    float* hb = hid + ((long)(b * 64 + h * 8)) * HW + pix;
    #pragma unroll 1
    for (int c = 0; c < CHN; c++) {
        ull nb[9];
        #pragma unroll
        for (int dy = 0; dy < 3; dy++) {
            const float* rp = &sv[c][tyy + dy][px0];
            const ull A  = *(const ull*)rp;
            const ull Cc = *(const ull*)(rp + 2);
            nb[dy * 3 + 0] = A;
            nb[dy * 3 + 1] = (A >> 32) | (Cc << 32);
            nb[dy * 3 + 2] = Cc;
        }
        ull o2 = 0ULL;
        #pragma unroll
        for (int a = 0; a < 9; a++) {
            const int ca = c * 9 + a;
            const ulonglong2 w01 = *(const ulonglong2*)&wp[ca][0];
            const ulonglong2 w23 = *(const ulonglong2*)&wp[ca][2];
            const ulonglong2 w45 = *(const ulonglong2*)&wp[ca][4];
            const ulonglong2 w67 = *(const ulonglong2*)&wp[ca][6];
            const ulonglong2 w8p = *(const ulonglong2*)&wp[ca][8];
            ull vv = bv2[ca];
            fma2(vv, w01.x, nb[0]); fma2(vv, w01.y, nb[1]);
            fma2(vv, w23.x, nb[2]); fma2(vv, w23.y, nb[3]);
            fma2(vv, w45.x, nb[4]); fma2(vv, w45.y, nb[5]);
            fma2(vv, w67.x, nb[6]); fma2(vv, w67.y, nb[7]);
            fma2(vv, w8p.x, nb[8]);
            fma2(o2, p2[a], vv);
        }
        float o0, o1; unpack2(o2, o0, o1);
        *(float2*)(hb + (long)c * HW) = make_float2(o0, o1);
    }
}

extern "C" void kernel_launch(void* const* d_in, const int* in_sizes, int n_in,
                              void* d_out, int out_size)
{
    const float* x      = (const float*)d_in[0];  // (16,256,56,56)
    const float* qkv_w  = (const float*)d_in[1];  // (192,256)
    const float* qkv_b  = (const float*)d_in[2];  // (192)
    const float* dc_b   = (const float*)d_in[3];  // (72)
    const float* dc1_w  = (const float*)d_in[4];  // (72,1,3,3)
    const float* dc1_b  = (const float*)d_in[5];  // (72)
    const float* rpb    = (const float*)d_in[6];  // (1,8,1,9,1,1)
    const float* proj_w = (const float*)d_in[7];  // (256,64)
    const float* proj_b = (const float*)d_in[8];  // (256)
    float* out = (float*)d_out;                   // (16,256,56,56)

    float *qkv_p, *hid_p;
    uint4 *wq_p, *wp_p;
    cudaGetSymbolAddress((void**)&qkv_p, g_qkv);
    cudaGetSymbolAddress((void**)&hid_p, g_hid);
    cudaGetSymbolAddress((void**)&wq_p,  g_wq);
    cudaGetSymbolAddress((void**)&wp_p,  g_wp);

    // 0) pre-pack weights (tiny)
    pack_w<<<96, 256>>>(qkv_w,  wq_p, 192, 256);
    pack_w<<<32, 256>>>(proj_w, wp_p, 256, 64);

    // smem: 2 x (A 10,240 + B NTILE*160)
    const int SMEM_QKV  = 2 * (2 * 64 * 80 + 2 * 192 * 80);  // 81,920
    const int SMEM_PROJ = 2 * (2 * 64 * 80 + 2 * 128 * 80);  // 61,440
    cudaFuncSetAttribute(gemm_hmma<192, 192, 256>,
                         cudaFuncAttributeMaxDynamicSharedMemorySize, SMEM_QKV);
    cudaFuncSetAttribute(gemm_hmma<128, 256, 64>,
                         cudaFuncAttributeMaxDynamicSharedMemorySize, SMEM_PROJ);

    // 1) QKV: C(192,3136) = qkv_w(192,256) @ x(256,3136), per batch
    gemm_hmma<192, 192, 256><<<dim3(49, 1, 16), 256, SMEM_QKV>>>(
        x, wq_p, qkv_b, qkv_p);

    // 2) Fused sliding attention
    attn2<<<dim3(WID / AT_ROWS, NHD, 16), 224>>>(
        qkv_p, dc_b, dc1_w, dc1_b, rpb, hid_p);

    // 3) Proj: out(256,3136) = proj_w(256,64) @ hid(64,3136), per batch
    gemm_hmma<128, 256, 64><<<dim3(49, 2, 16), 256, SMEM_PROJ>>>(
        hid_p, wp_p, proj_b, out);
}

// round 14
// speedup vs baseline: 1.1283x; 1.0495x over previous
#include <cuda_runtime.h>
#include <cuda_bf16.h>
#include <cstdint>

typedef unsigned long long ull;

#define HW   3136
#define WID  56
#define NHD  8
#define CHN  8
#define SCALE 0.17677669529663687f  // (256/8)^-0.5

// Scratch (alloc-free rule: __device__ globals)
__device__ float g_qkv[16 * 192 * HW];   // (B, 192, H*W)
__device__ float g_hid[16 * 64  * HW];   // (B, 64, H*W)
// Pre-packed bf16 hi/lo weight images (smem layout chunks)
__device__ uint4 g_wq[(256 / 32) * 192 * 8];   // qkv_w packed
__device__ uint4 g_wp[(64  / 32) * 256 * 8];   // proj_w packed

// ---------------------------------------------------------------------------
// helpers
// ---------------------------------------------------------------------------
__device__ __forceinline__ ull pack2(float x) {
    ull r; unsigned u = __float_as_uint(x);
    asm("mov.b64 %0, {%1, %1};" : "=l"(r) : "r"(u));
    return r;
}
__device__ __forceinline__ ull pack2f(float a, float b) {
    ull r;
    asm("mov.b64 %0, {%1, %2};" : "=l"(r) : "f"(a), "f"(b));
    return r;
}
__device__ __forceinline__ void unpack2(ull v, float &a, float &b) {
    asm("mov.b64 {%0, %1}, %2;" : "=f"(a), "=f"(b) : "l"(v));
}
__device__ __forceinline__ void fma2(ull &d, ull a, ull b) {
    asm("fma.rn.f32x2 %0, %1, %2, %3;" : "=l"(d) : "l"(a), "l"(b), "l"(d));
}
__device__ __forceinline__ uint32_t smem_u32(const void* p) {
    uint32_t a;
    asm("{ .reg .u64 t; cvta.to.shared.u64 t, %1; cvt.u32.u64 %0, t; }"
        : "=r"(a) : "l"(p));
    return a;
}
__device__ __forceinline__ void split2(float x, float y, unsigned &hi2, unsigned &lo2) {
    __nv_bfloat16 xh = __float2bfloat16_rn(x);
    __nv_bfloat16 yh = __float2bfloat16_rn(y);
    float xr = x - __bfloat162float(xh);
    float yr = y - __bfloat162float(yh);
    __nv_bfloat162 h2 = __halves2bfloat162(xh, yh);
    __nv_bfloat162 l2 = __halves2bfloat162(__float2bfloat16_rn(xr), __float2bfloat16_rn(yr));
    hi2 = *reinterpret_cast<unsigned*>(&h2);
    lo2 = *reinterpret_cast<unsigned*>(&l2);
}
__device__ __forceinline__ void ldsm4(uint32_t (&r)[4], uint32_t addr) {
    asm volatile("ldmatrix.sync.aligned.m8n8.x4.shared.b16 {%0,%1,%2,%3}, [%4];"
        : "=r"(r[0]), "=r"(r[1]), "=r"(r[2]), "=r"(r[3]) : "r"(addr));
}
__device__ __forceinline__ void mma16816(float (&d)[4], const uint32_t (&a)[4],
                                         uint32_t b0, uint32_t b1) {
    asm volatile(
        "mma.sync.aligned.m16n8k16.row.col.f32.bf16.bf16.f32 "
        "{%0,%1,%2,%3}, {%4,%5,%6,%7}, {%8,%9}, {%0,%1,%2,%3};"
        : "+f"(d[0]), "+f"(d[1]), "+f"(d[2]), "+f"(d[3])
        : "r"(a[0]), "r"(a[1]), "r"(a[2]), "r"(a[3]), "r"(b0), "r"(b1));
}
__device__ __forceinline__ void sts128(uint32_t addr, unsigned a, unsigned b,
                                       unsigned c, unsigned d) {
    asm volatile("st.shared.v4.b32 [%0], {%1,%2,%3,%4};"
                 :: "r"(addr), "r"(a), "r"(b), "r"(c), "r"(d));
}

// ---------------------------------------------------------------------------
// W pre-pack (unchanged from R12)
// ---------------------------------------------------------------------------
__global__ void pack_w(const float* __restrict__ W, uint4* __restrict__ dst,
                       int NCH, int KTOT)
{
    const int idx = blockIdx.x * 256 + threadIdx.x;
    const int npairs = NCH * (KTOT >> 1);
    if (idx >= npairs) return;
    const int ch = idx / (KTOT >> 1);
    const int pr = idx - ch * (KTOT >> 1);
    const int t  = pr >> 4;
    const int p  = pr & 15;
    unsigned h, l;
    split2(W[ch * KTOT + 2 * pr], W[ch * KTOT + 2 * pr + 1], h, l);
    uint32_t* d32 = (uint32_t*)dst;
    const uint32_t base = (uint32_t)(t * NCH * 32 + ch * 16 + p);
    d32[base] = h;
    d32[base + NCH * 16] = l;
}

// ---------------------------------------------------------------------------
// HMMA bf16x3 GEMM (unchanged from R12)
// ---------------------------------------------------------------------------
template<int NTILE, int NCHTOT, int KTOT>
__global__ void __launch_bounds__(256, 2)
gemm_hmma(const float* __restrict__ X, const uint4* __restrict__ Wp,
          const float* __restrict__ bias, float* __restrict__ C)
{
    constexpr int KT     = KTOT / 32;
    constexpr int WN     = NTILE / 4;
    constexpr int NFRAG  = WN / 8;
    constexpr int NPAIR  = NFRAG / 2;
    constexpr int ABUF   = 2 * 64 * 80;
    constexpr int BROW   = NTILE * 80;
    constexpr int BBUF   = 2 * BROW;
    constexpr int BOFF   = 2 * ABUF;
    constexpr int WCHUNK = NTILE / 32;

    extern __shared__ char dyn[];
    const uint32_t sb = smem_u32(dyn);

    const int tid  = threadIdx.x;
    const int wid  = tid >> 5;
    const int lane = tid & 31;
    const int wm   = wid & 1;
    const int wn   = wid >> 1;
    const int m0   = blockIdx.x * 64;
    const int n0   = blockIdx.y * NTILE;
    const int b    = blockIdx.z;

    const float* Xb = X + (long)b * KTOT * HW;
    float*       Cb = C + (long)b * NCHTOT * HW;

    const int px  = tid & 63;
    const int khx = tid >> 6;
    const float* xPtr = Xb + (long)(khx * 8) * HW + m0 + px;

    float acc[2][NFRAG][4];
    #pragma unroll
    for (int i = 0; i < 2; i++)
        #pragma unroll
        for (int j = 0; j < NFRAG; j++)
            #pragma unroll
            for (int e = 0; e < 4; e++) acc[i][j][e] = 0.f;

    float xv[8];
    uint4 wq[WCHUNK];

    auto loadRegs = [&](int t) {
        const float* xp = xPtr + (long)(t * 32) * HW;
        #pragma unroll
        for (int j = 0; j < 8; j++)
            xv[j] = xp[(long)j * HW];
        #pragma unroll
        for (int i = 0; i < WCHUNK; i++) {
            const int c     = tid + (i << 8);
            const int plane = c >= NTILE * 4;
            const int rc    = c - plane * NTILE * 4;
            const int row   = rc >> 2;
            const int seg   = rc & 3;
            wq[i] = Wp[t * (NCHTOT * 8) + plane * (NCHTOT * 4) + (n0 + row) * 4 + seg];
        }
    };
    auto stsTile = [&](int buf) {
        const uint32_t Ahi = sb + buf * ABUF;
        const uint32_t Alo = Ahi + 64 * 80;
        {
            unsigned h[4], l[4];
            #pragma unroll
            for (int k2 = 0; k2 < 4; k2++)
                split2(xv[2 * k2], xv[2 * k2 + 1], h[k2], l[k2]);
            const uint32_t off = (uint32_t)(px * 80 + khx * 16);
            sts128(Ahi + off, h[0], h[1], h[2], h[3]);
            sts128(Alo + off, l[0], l[1], l[2], l[3]);
        }
        const uint32_t Bhi = sb + BOFF + buf * BBUF;
        const uint32_t Blo = Bhi + BROW;
        #pragma unroll
        for (int i = 0; i < WCHUNK; i++) {
            const int c     = tid + (i << 8);
            const int plane = c >= NTILE * 4;
            const int rc    = c - plane * NTILE * 4;
            const int row   = rc >> 2;
            const int seg   = rc & 3;
            const uint32_t addr = (plane ? Blo : Bhi) + (uint32_t)(row * 80 + seg * 16);
            sts128(addr, wq[i].x, wq[i].y, wq[i].z, wq[i].w);
        }
    };
    auto compute = [&](int buf) {
        const uint32_t Ahi = sb + buf * ABUF;
        const uint32_t Alo = Ahi + 64 * 80;
        const uint32_t Bhi = sb + BOFF + buf * BBUF;
        const uint32_t Blo = Bhi + BROW;
        const int lrow = lane & 15;
        const uint32_t kb0 = (uint32_t)((lane >> 4) << 4);
        #pragma unroll
        for (int s = 0; s < 2; s++) {
            const uint32_t kb = kb0 + 32 * s;
            uint32_t ah[2][4], al[2][4];
            #pragma unroll
            for (int mf = 0; mf < 2; mf++) {
                const uint32_t ro = (uint32_t)((wm * 32 + mf * 16 + lrow) * 80) + kb;
                ldsm4(ah[mf], Ahi + ro);
                ldsm4(al[mf], Alo + ro);
            }
            #pragma unroll
            for (int j = 0; j < NPAIR; j++) {
                const uint32_t ro = (uint32_t)((wn * WN + j * 16 + lrow) * 80) + kb;
                uint32_t bh[4], bl[4];
                ldsm4(bh, Bhi + ro);
                ldsm4(bl, Blo + ro);
                #pragma unroll
                for (int mf = 0; mf < 2; mf++) {
                    mma16816(acc[mf][2*j],   ah[mf], bh[0], bh[2]);
                    mma16816(acc[mf][2*j+1], ah[mf], bh[1], bh[3]);
                    mma16816(acc[mf][2*j],   ah[mf], bl[0], bl[2]);
                    mma16816(acc[mf][2*j+1], ah[mf], bl[1], bl[3]);
                    mma16816(acc[mf][2*j],   al[mf], bh[0], bh[2]);
                    mma16816(acc[mf][2*j+1], al[mf], bh[1], bh[3]);
                }
            }
        }
    };

    loadRegs(0);
    stsTile(0);
    __syncthreads();
    for (int t = 0; t < KT; t++) {
        if (t + 1 < KT) loadRegs(t + 1);
        compute(t & 1);
        if (t + 1 < KT) {
            stsTile((t + 1) & 1);
            __syncthreads();
        }
    }

    const int r0 = lane >> 2;
    const int c0 = 2 * (lane & 3);
    #pragma unroll
    for (int nf = 0; nf < NFRAG; nf++) {
        const int ch = n0 + wn * WN + nf * 8 + c0;
        const float b0 = bias[ch], b1 = bias[ch + 1];
        float* p0 = Cb + (long)ch * HW;
        float* p1 = p0 + HW;
        #pragma unroll
        for (int mf = 0; mf < 2; mf++) {
            const int pr = m0 + wm * 32 + mf * 16 + r0;
            p0[pr]     = acc[mf][nf][0] + b0;
            p1[pr]     = acc[mf][nf][1] + b1;
            p0[pr + 8] = acc[mf][nf][2] + b0;
            p1[pr + 8] = acc[mf][nf][3] + b1;
        }
    }
}

// ---------------------------------------------------------------------------
// Fused sliding attention v3: TWO HEADS per block share every weight load.
// (dc1_w/dc_b/dc1_b are head-independent; only rpb differs -> bk2 per head.)
// Block = 56x8 pixel tile, heads (2h, 2h+1), batch b; 224 threads,
// 2 pixels/thread/head. Per (c,a): 6-7 LDS feed 20 fma2 (was 10).
// ---------------------------------------------------------------------------
#define AT_ROWS 8
#define AT_HROW (AT_ROWS + 2)
#define AT_CH_F (CHN * AT_HROW * 58)           // 4640 floats per k/v plane
#define AT_SMEM (4 * AT_CH_F * 4 + (720 + 72 + 72 + 72) * 8)   // 81,728 B

__global__ void __launch_bounds__(224)
attn3(const float* __restrict__ qkv,
      const float* __restrict__ dc_b,
      const float* __restrict__ dc1_w,
      const float* __restrict__ dc1_b,
      const float* __restrict__ rpb,
      float* __restrict__ hid)
{
    extern __shared__ __align__(16) char dynsm[];
    float* sk0 = (float*)dynsm;
    float* sv0 = sk0 + AT_CH_F;
    float* sk1 = sv0 + AT_CH_F;
    float* sv1 = sk1 + AT_CH_F;
    ull*   wp  = (ull*)(sk0 + 4 * AT_CH_F);    // [72][10], 16B-aligned rows
    ull*   bkA = wp + 720;                     // k bias head0
    ull*   bkB = bkA + 72;                     // k bias head1
    ull*   bv2 = bkB + 72;                     // v bias (shared)

    const int tid = threadIdx.x;
    const int h0  = blockIdx.y * 2;
    const int b   = blockIdx.z;
    const int y0  = blockIdx.x * AT_ROWS;

    if (tid < 72) {
        const int a = tid - (tid / 9) * 9;
        const float cb = dc_b[tid] + dc1_b[tid];
        bv2[tid] = pack2(cb);
        bkA[tid] = pack2(cb + rpb[h0 * 9 + a]);
        bkB[tid] = pack2(cb + rpb[h0 * 9 + 9 + a]);
        #pragma unroll
        for (int t = 0; t < 9; t++) {
            float w = dc1_w[tid * 9 + t] + ((t == a) ? 1.f : 0.f);
            wp[tid * 10 + t] = pack2(w);
        }
        wp[tid * 10 + 9] = 0ULL;
    }

    {   // halo load, both heads
        const float* baseA = qkv + ((long)(b * 192 + h0 * 24 + 8)) * HW;
        for (int i = tid; i < AT_HROW * 58; i += 224) {
            const int r = i / 58, s = i - r * 58;
            const int gy = y0 - 1 + r, gx = s - 1;
            const bool ok = (gy >= 0) & (gy < WID) & (gx >= 0) & (gx < WID);
            const int off = ok ? gy * WID + gx : 0;
            #pragma unroll
            for (int c = 0; c < CHN; c++) {
                const int si = (c * AT_HROW + r) * 58 + s;
                sk0[si] = ok ? baseA[c * HW + off]               : 0.f;
                sv0[si] = ok ? baseA[(8 + c) * HW + off]         : 0.f;
                sk1[si] = ok ? baseA[(24 + c) * HW + off]        : 0.f;
                sv1[si] = ok ? baseA[(32 + c) * HW + off]        : 0.f;
            }
        }
    }

    const int tx  = tid % 28;
    const int tyy = tid / 28;
    const int px0 = tx * 2;
    const int pix = (y0 + tyy) * WID + px0;

    const float* qp0 = qkv + ((long)(b * 192 + h0 * 24)) * HW + pix;
    const float* qp1 = qp0 + 24 * HW;
    __syncthreads();

    // ---- K phase: logits for both heads ----
    ull logA[9], logB[9];
    #pragma unroll
    for (int a = 0; a < 9; a++) { logA[a] = 0ULL; logB[a] = 0ULL; }

    float2 qA = *(const float2*)qp0;
    float2 qB = *(const float2*)qp1;

    #pragma unroll 1
    for (int c = 0; c < CHN; c++) {
        const ull q2A = pack2f(qA.x * SCALE, qA.y * SCALE);
        const ull q2B = pack2f(qB.x * SCALE, qB.y * SCALE);
        if (c < 7) {
            qA = *(const float2*)(qp0 + (long)(c + 1) * HW);
            qB = *(const float2*)(qp1 + (long)(c + 1) * HW);
        }
        ull nA[9], nB[9];
        #pragma unroll
        for (int dy = 0; dy < 3; dy++) {
            const int ro = (c * AT_HROW + tyy + dy) * 58 + px0;
            const ull A0 = *(const ull*)(sk0 + ro);
            const ull C0 = *(const ull*)(sk0 + ro + 2);
            nA[dy * 3 + 0] = A0;
            nA[dy * 3 + 1] = (A0 >> 32) | (C0 << 32);
            nA[dy * 3 + 2] = C0;
            const ull A1 = *(const ull*)(sk1 + ro);
            const ull C1 = *(const ull*)(sk1 + ro + 2);
            nB[dy * 3 + 0] = A1;
            nB[dy * 3 + 1] = (A1 >> 32) | (C1 << 32);
            nB[dy * 3 + 2] = C1;
        }
        #pragma unroll
        for (int a = 0; a < 9; a++) {
            const int ca = c * 9 + a;
            const ulonglong2 w01 = *(const ulonglong2*)(wp + ca * 10);
            const ulonglong2 w23 = *(const ulonglong2*)(wp + ca * 10 + 2);
            const ulonglong2 w45 = *(const ulonglong2*)(wp + ca * 10 + 4);
            const ulonglong2 w67 = *(const ulonglong2*)(wp + ca * 10 + 6);
            const ulonglong2 w8p = *(const ulonglong2*)(wp + ca * 10 + 8);
            ull kvA = bkA[ca];
            ull kvB = bkB[ca];
            fma2(kvA, w01.x, nA[0]); fma2(kvB, w01.x, nB[0]);
            fma2(kvA, w01.y, nA[1]); fma2(kvB, w01.y, nB[1]);
            fma2(kvA, w23.x, nA[2]); fma2(kvB, w23.x, nB[2]);
            fma2(kvA, w23.y, nA[3]); fma2(kvB, w23.y, nB[3]);
            fma2(kvA, w45.x, nA[4]); fma2(kvB, w45.x, nB[4]);
            fma2(kvA, w45.y, nA[5]); fma2(kvB, w45.y, nB[5]);
            fma2(kvA, w67.x, nA[6]); fma2(kvB, w67.x, nB[6]);
            fma2(kvA, w67.y, nA[7]); fma2(kvB, w67.y, nB[7]);
            fma2(kvA, w8p.x, nA[8]); fma2(kvB, w8p.x, nB[8]);
            fma2(logA[a], q2A, kvA);
            fma2(logB[a], q2B, kvB);
        }
    }

    // ---- softmax, both heads (2 pixels each) ----
    ull pA[9], pB[9];
    {
        float a0[9], a1[9], b0[9], b1[9];
        #pragma unroll
        for (int a = 0; a < 9; a++) { unpack2(logA[a], a0[a], a1[a]);
                                      unpack2(logB[a], b0[a], b1[a]); }
        float mA0 = a0[0], mA1 = a1[0], mB0 = b0[0], mB1 = b1[0];
        #pragma unroll
        for (int a = 1; a < 9; a++) {
            mA0 = fmaxf(mA0, a0[a]); mA1 = fmaxf(mA1, a1[a]);
            mB0 = fmaxf(mB0, b0[a]); mB1 = fmaxf(mB1, b1[a]);
        }
        float sA0 = 0.f, sA1 = 0.f, sB0 = 0.f, sB1 = 0.f;
        #pragma unroll
        for (int a = 0; a < 9; a++) {
            a0[a] = __expf(a0[a] - mA0); sA0 += a0[a];
            a1[a] = __expf(a1[a] - mA1); sA1 += a1[a];
            b0[a] = __expf(b0[a] - mB0); sB0 += b0[a];
            b1[a] = __expf(b1[a] - mB1); sB1 += b1[a];
        }
        const float iA0 = 1.f / sA0, iA1 = 1.f / sA1;
        const float iB0 = 1.f / sB0, iB1 = 1.f / sB1;
        #pragma unroll
        for (int a = 0; a < 9; a++) {
            pA[a] = pack2f(a0[a] * iA0, a1[a] * iA1);
            pB[a] = pack2f(b0[a] * iB0, b1[a] * iB1);
        }
    }

    // ---- V phase: outputs for both heads ----
    float* hb0 = hid + ((long)(b * 64 + h0 * 8)) * HW + pix;
    float* hb1 = hb0 + 8 * HW;
    #pragma unroll 1
    for (int c = 0; c < CHN; c++) {
        ull nA[9], nB[9];
        #pragma unroll
        for (int dy = 0; dy < 3; dy++) {
            const int ro = (c * AT_HROW + tyy + dy) * 58 + px0;
            const ull A0 = *(const ull*)(sv0 + ro);
            const ull C0 = *(const ull*)(sv0 + ro + 2);
            nA[dy * 3 + 0] = A0;
            nA[dy * 3 + 1] = (A0 >> 32) | (C0 << 32);
            nA[dy * 3 + 2] = C0;
            const ull A1 = *(const ull*)(sv1 + ro);
            const ull C1 = *(const ull*)(sv1 + ro + 2);
            nB[dy * 3 + 0] = A1;
            nB[dy * 3 + 1] = (A1 >> 32) | (C1 << 32);
            nB[dy * 3 + 2] = C1;
        }
        ull oA = 0ULL, oB = 0ULL;
        #pragma unroll
        for (int a = 0; a < 9; a++) {
            const int ca = c * 9 + a;
            const ulonglong2 w01 = *(const ulonglong2*)(wp + ca * 10);
            const ulonglong2 w23 = *(const ulonglong2*)(wp + ca * 10 + 2);
            const ulonglong2 w45 = *(const ulonglong2*)(wp + ca * 10 + 4);
            const ulonglong2 w67 = *(const ulonglong2*)(wp + ca * 10 + 6);
            const ulonglong2 w8p = *(const ulonglong2*)(wp + ca * 10 + 8);
            ull vA = bv2[ca];
            ull vB = vA;
            fma2(vA, w01.x, nA[0]); fma2(vB, w01.x, nB[0]);
            fma2(vA, w01.y, nA[1]); fma2(vB, w01.y, nB[1]);
            fma2(vA, w23.x, nA[2]); fma2(vB, w23.x, nB[2]);
            fma2(vA, w23.y, nA[3]); fma2(vB, w23.y, nB[3]);
            fma2(vA, w45.x, nA[4]); fma2(vB, w45.x, nB[4]);
            fma2(vA, w45.y, nA[5]); fma2(vB, w45.y, nB[5]);
            fma2(vA, w67.x, nA[6]); fma2(vB, w67.x, nB[6]);
            fma2(vA, w67.y, nA[7]); fma2(vB, w67.y, nB[7]);
            fma2(vA, w8p.x, nA[8]); fma2(vB, w8p.x, nB[8]);
            fma2(oA, pA[a], vA);
            fma2(oB, pB[a], vB);
        }
        float x0, x1; unpack2(oA, x0, x1);
        *(float2*)(hb0 + (long)c * HW) = make_float2(x0, x1);
        unpack2(oB, x0, x1);
        *(float2*)(hb1 + (long)c * HW) = make_float2(x0, x1);
    }
}

extern "C" void kernel_launch(void* const* d_in, const int* in_sizes, int n_in,
                              void* d_out, int out_size)
{
    const float* x      = (const float*)d_in[0];  // (16,256,56,56)
    const float* qkv_w  = (const float*)d_in[1];  // (192,256)
    const float* qkv_b  = (const float*)d_in[2];  // (192)
    const float* dc_b   = (const float*)d_in[3];  // (72)
    const float* dc1_w  = (const float*)d_in[4];  // (72,1,3,3)
    const float* dc1_b  = (const float*)d_in[5];  // (72)
    const float* rpb    = (const float*)d_in[6];  // (1,8,1,9,1,1)
    const float* proj_w = (const float*)d_in[7];  // (256,64)
    const float* proj_b = (const float*)d_in[8];  // (256)
    float* out = (float*)d_out;                   // (16,256,56,56)

    float *qkv_p, *hid_p;
    uint4 *wq_p, *wp_p;
    cudaGetSymbolAddress((void**)&qkv_p, g_qkv);
    cudaGetSymbolAddress((void**)&hid_p, g_hid);
    cudaGetSymbolAddress((void**)&wq_p,  g_wq);
    cudaGetSymbolAddress((void**)&wp_p,  g_wp);

    // 0) pre-pack weights (tiny)
    pack_w<<<96, 256>>>(qkv_w,  wq_p, 192, 256);
    pack_w<<<32, 256>>>(proj_w, wp_p, 256, 64);

    const int SMEM_QKV  = 2 * (2 * 64 * 80 + 2 * 192 * 80);  // 81,920
    const int SMEM_PROJ = 2 * (2 * 64 * 80 + 2 * 128 * 80);  // 61,440
    cudaFuncSetAttribute(gemm_hmma<192, 192, 256>,
                         cudaFuncAttributeMaxDynamicSharedMemorySize, SMEM_QKV);
    cudaFuncSetAttribute(gemm_hmma<128, 256, 64>,
                         cudaFuncAttributeMaxDynamicSharedMemorySize, SMEM_PROJ);
    cudaFuncSetAttribute(attn3,
                         cudaFuncAttributeMaxDynamicSharedMemorySize, AT_SMEM);

    // 1) QKV: C(192,3136) = qkv_w(192,256) @ x(256,3136), per batch
    gemm_hmma<192, 192, 256><<<dim3(49, 1, 16), 256, SMEM_QKV>>>(
        x, wq_p, qkv_b, qkv_p);

    // 2) Fused sliding attention — 2 heads per block
    attn3<<<dim3(WID / AT_ROWS, NHD / 2, 16), 224, AT_SMEM>>>(
        qkv_p, dc_b, dc1_w, dc1_b, rpb, hid_p);

    // 3) Proj: out(256,3136) = proj_w(256,64) @ hid(64,3136), per batch
    gemm_hmma<128, 256, 64><<<dim3(49, 2, 16), 256, SMEM_PROJ>>>(
        hid_p, wp_p, proj_b, out);
}